// round 3
// baseline (speedup 1.0000x reference)
#include <cuda_runtime.h>
#include <cuda_fp16.h>

#define N_MAX   100000
#define E_MAX   1600000
#define NFEAT   128
#define NHID    64
#define NCLS    40

// ---------------- device scratch (allocation-free) ----------------
__device__ int   g_is64;
__device__ int   g_src[E_MAX];
__device__ int   g_dst[E_MAX];
__device__ int   g_csr[E_MAX];
__device__ int   g_deg[N_MAX];
__device__ int   g_off[N_MAX];
__device__ int   g_cur[N_MAX];
__device__ int   g_bsum[512];
__device__ uint4 g_h1h[N_MAX * 8];    // h1 [N,64] fp16
__device__ uint4 g_r1 [N_MAX * 8];    // relu(agg1/cnt) [N,64] fp16
__device__ uint2 g_h2h[N_MAX * 10];   // h2 [N,40] fp16

// ---------------- pre: zero deg + dtype detect ----------------
__global__ void k_pre(const unsigned* __restrict__ ei, int n) {
    int i = blockIdx.x * blockDim.x + threadIdx.x;
    if (i < n) g_deg[i] = 0;
    if (i == 0) {
        unsigned hi = 0;
        #pragma unroll
        for (int j = 1; j < 64; j += 2) hi |= ei[j];
        g_is64 = (hi == 0u) ? 1 : 0;
    }
}

// ---------------- hist: edges -> int32 + degree histogram ----------
__global__ void k_hist(const void* __restrict__ ei, int E) {
    int i = blockIdx.x * blockDim.x + threadIdx.x;
    if (i >= E) return;
    int s, d;
    if (g_is64) {
        const long long* p = (const long long*)ei;
        s = (int)p[i]; d = (int)p[E + i];
    } else {
        const int* p = (const int*)ei;
        s = p[i]; d = p[E + i];
    }
    g_src[i] = s;
    g_dst[i] = d;
    atomicAdd(&g_deg[d], 1);
}

// ---------------- scan1: block-local exclusive scan of deg ----------
__global__ __launch_bounds__(256) void k_scan1(int n) {
    int i = blockIdx.x * 256 + threadIdx.x;
    int v = (i < n) ? g_deg[i] : 0;
    int lane = threadIdx.x & 31, w = threadIdx.x >> 5;
    int s = v;
    #pragma unroll
    for (int o = 1; o < 32; o <<= 1) {
        int t = __shfl_up_sync(0xFFFFFFFFu, s, o);
        if (lane >= o) s += t;
    }
    __shared__ int wsum[8];
    if (lane == 31) wsum[w] = s;
    __syncthreads();
    if (w == 0) {
        int t = (lane < 8) ? wsum[lane] : 0;
        #pragma unroll
        for (int o = 1; o < 8; o <<= 1) {
            int u = __shfl_up_sync(0xFFFFFFFFu, t, o);
            if (lane >= o) t += u;
        }
        if (lane < 8) wsum[lane] = t;
    }
    __syncthreads();
    int incl = s + (w > 0 ? wsum[w - 1] : 0);
    if (i < n) g_off[i] = incl - v;
    if (threadIdx.x == 255) g_bsum[blockIdx.x] = incl;
}

// ---------------- scan2: scan of block sums (nb <= 512) -------------
__global__ __launch_bounds__(512) void k_scan2(int nb) {
    int t = threadIdx.x;
    int v = (t < nb) ? g_bsum[t] : 0;
    int lane = t & 31, w = t >> 5;
    int s = v;
    #pragma unroll
    for (int o = 1; o < 32; o <<= 1) {
        int u = __shfl_up_sync(0xFFFFFFFFu, s, o);
        if (lane >= o) s += u;
    }
    __shared__ int wsum[16];
    if (lane == 31) wsum[w] = s;
    __syncthreads();
    if (w == 0) {
        int u = (lane < 16) ? wsum[lane] : 0;
        #pragma unroll
        for (int o = 1; o < 16; o <<= 1) {
            int q = __shfl_up_sync(0xFFFFFFFFu, u, o);
            if (lane >= o) u += q;
        }
        if (lane < 16) wsum[lane] = u;
    }
    __syncthreads();
    int incl = s + (w > 0 ? wsum[w - 1] : 0);
    if (t < nb) g_bsum[t] = incl - v;   // exclusive
}

// ---------------- scan3: add block offsets, init cursors -------------
__global__ void k_scan3(int n) {
    int i = blockIdx.x * blockDim.x + threadIdx.x;
    if (i >= n) return;
    int off = g_off[i] + g_bsum[i >> 8];
    g_off[i] = off;
    g_cur[i] = off;
}

// ---------------- csr: scatter src ids into CSR order ----------------
__global__ void k_csr(int E) {
    int i = blockIdx.x * blockDim.x + threadIdx.x;
    if (i >= E) return;
    int d = g_dst[i];
    int pos = atomicAdd(&g_cur[d], 1);
    g_csr[pos] = g_src[i];
}

// ---------------- GEMM1: h1 = x @ W1^T + b1 -> [N,64] fp16 -----------
__global__ __launch_bounds__(256) void k_gemm1(
    const float* __restrict__ x, const float* __restrict__ W,
    const float* __restrict__ b, int n)
{
    __shared__ __align__(16) float xs[64][68];
    __shared__ __align__(16) float ws[64][68];
    int tid  = threadIdx.x;
    int row0 = blockIdx.x * 64;
    int tx = tid & 15, ty = tid >> 4;

    float acc[4][4];
    #pragma unroll
    for (int i = 0; i < 4; ++i)
        #pragma unroll
        for (int j = 0; j < 4; ++j) acc[i][j] = 0.f;

    for (int kk = 0; kk < NFEAT; kk += 64) {
        #pragma unroll
        for (int it = 0; it < 4; ++it) {
            int idx = tid + it * 256;
            int r = idx >> 4, k4 = idx & 15;
            float4 v = make_float4(0.f, 0.f, 0.f, 0.f);
            int row = row0 + r;
            if (row < n)
                v = __ldg((const float4*)(x + (size_t)row * NFEAT + kk) + k4);
            xs[k4 * 4 + 0][r] = v.x; xs[k4 * 4 + 1][r] = v.y;
            xs[k4 * 4 + 2][r] = v.z; xs[k4 * 4 + 3][r] = v.w;
        }
        #pragma unroll
        for (int it = 0; it < 4; ++it) {
            int idx = tid + it * 256;
            int c = idx >> 4, k4 = idx & 15;
            float4 v = __ldg((const float4*)(W + (size_t)c * NFEAT + kk) + k4);
            ws[k4 * 4 + 0][c] = v.x; ws[k4 * 4 + 1][c] = v.y;
            ws[k4 * 4 + 2][c] = v.z; ws[k4 * 4 + 3][c] = v.w;
        }
        __syncthreads();
        #pragma unroll
        for (int k = 0; k < 64; ++k) {
            float4 xv = *(const float4*)&xs[k][ty * 4];
            float4 wv = *(const float4*)&ws[k][tx * 4];
            float ax[4] = {xv.x, xv.y, xv.z, xv.w};
            float aw[4] = {wv.x, wv.y, wv.z, wv.w};
            #pragma unroll
            for (int i = 0; i < 4; ++i)
                #pragma unroll
                for (int j = 0; j < 4; ++j) acc[i][j] += ax[i] * aw[j];
        }
        __syncthreads();
    }

    float4 bb = __ldg((const float4*)b + tx);
    #pragma unroll
    for (int i = 0; i < 4; ++i) {
        int row = row0 + ty * 4 + i;
        if (row < n) {
            __half2 p0 = __floats2half2_rn(acc[i][0] + bb.x, acc[i][1] + bb.y);
            __half2 p1 = __floats2half2_rn(acc[i][2] + bb.z, acc[i][3] + bb.w);
            uint2 o;
            o.x = *(unsigned*)&p0; o.y = *(unsigned*)&p1;
            ((uint2*)g_h1h)[row * 16 + tx] = o;
        }
    }
}

// ---------- agg1: r1 = relu((h1[row] + sum h1[csr]) / (deg+1)) -------
// warp/row, 8 lanes/edge, 4 edges per iteration, fp32 accumulation
__global__ __launch_bounds__(256) void k_agg1(int n) {
    int row = (blockIdx.x * 256 + threadIdx.x) >> 5;
    if (row >= n) return;
    int lane = threadIdx.x & 31, grp = lane >> 3, sub = lane & 7;
    int start = g_off[row], deg = g_deg[row], end = start + deg;

    float acc[8];
    #pragma unroll
    for (int i = 0; i < 8; ++i) acc[i] = 0.f;

    for (int j = start + grp; j < end; j += 4) {
        int s = __ldg(&g_csr[j]);
        uint4 v = __ldg(&g_h1h[s * 8 + sub]);
        float2 f0 = __half22float2(*(__half2*)&v.x);
        float2 f1 = __half22float2(*(__half2*)&v.y);
        float2 f2 = __half22float2(*(__half2*)&v.z);
        float2 f3 = __half22float2(*(__half2*)&v.w);
        acc[0] += f0.x; acc[1] += f0.y; acc[2] += f1.x; acc[3] += f1.y;
        acc[4] += f2.x; acc[5] += f2.y; acc[6] += f3.x; acc[7] += f3.y;
    }
    #pragma unroll
    for (int i = 0; i < 8; ++i) {
        acc[i] += __shfl_xor_sync(0xFFFFFFFFu, acc[i], 8);
        acc[i] += __shfl_xor_sync(0xFFFFFFFFu, acc[i], 16);
    }
    if (grp == 0) {
        float inv = 1.0f / (float)(deg + 1);
        uint4 h = g_h1h[row * 8 + sub];
        float2 f0 = __half22float2(*(__half2*)&h.x);
        float2 f1 = __half22float2(*(__half2*)&h.y);
        float2 f2 = __half22float2(*(__half2*)&h.z);
        float2 f3 = __half22float2(*(__half2*)&h.w);
        float r0 = fmaxf((acc[0] + f0.x) * inv, 0.f);
        float r1 = fmaxf((acc[1] + f0.y) * inv, 0.f);
        float r2 = fmaxf((acc[2] + f1.x) * inv, 0.f);
        float r3 = fmaxf((acc[3] + f1.y) * inv, 0.f);
        float r4 = fmaxf((acc[4] + f2.x) * inv, 0.f);
        float r5 = fmaxf((acc[5] + f2.y) * inv, 0.f);
        float r6 = fmaxf((acc[6] + f3.x) * inv, 0.f);
        float r7 = fmaxf((acc[7] + f3.y) * inv, 0.f);
        __half2 p0 = __floats2half2_rn(r0, r1);
        __half2 p1 = __floats2half2_rn(r2, r3);
        __half2 p2 = __floats2half2_rn(r4, r5);
        __half2 p3 = __floats2half2_rn(r6, r7);
        uint4 o;
        o.x = *(unsigned*)&p0; o.y = *(unsigned*)&p1;
        o.z = *(unsigned*)&p2; o.w = *(unsigned*)&p3;
        g_r1[row * 8 + sub] = o;
    }
}

// ---------------- GEMM2: h2 = r1 @ W2^T + b2 -> [N,40] fp16 ----------
__global__ __launch_bounds__(160) void k_gemm2(
    const float* __restrict__ W, const float* __restrict__ b, int n)
{
    __shared__ __align__(16) float rs[64][68];
    __shared__ __align__(16) float ws[64][44];
    int tid  = threadIdx.x;
    int row0 = blockIdx.x * 64;

    for (int idx = tid; idx < 1024; idx += 160) {
        int r = idx >> 4, k4 = idx & 15;
        int row = row0 + r;
        float4 v = make_float4(0.f, 0.f, 0.f, 0.f);
        if (row < n) {
            uint2 a = ((const uint2*)g_r1)[row * 16 + k4];
            float2 f0 = __half22float2(*(__half2*)&a.x);
            float2 f1 = __half22float2(*(__half2*)&a.y);
            v.x = f0.x; v.y = f0.y; v.z = f1.x; v.w = f1.y;
        }
        rs[k4 * 4 + 0][r] = v.x; rs[k4 * 4 + 1][r] = v.y;
        rs[k4 * 4 + 2][r] = v.z; rs[k4 * 4 + 3][r] = v.w;
    }
    for (int idx = tid; idx < 640; idx += 160) {
        int c = idx >> 4, k4 = idx & 15;
        float4 v = __ldg((const float4*)(W + (size_t)c * NHID) + k4);
        ws[k4 * 4 + 0][c] = v.x; ws[k4 * 4 + 1][c] = v.y;
        ws[k4 * 4 + 2][c] = v.z; ws[k4 * 4 + 3][c] = v.w;
    }
    __syncthreads();

    int tx = tid % 10, ty = tid / 10;
    float acc[4][4];
    #pragma unroll
    for (int i = 0; i < 4; ++i)
        #pragma unroll
        for (int j = 0; j < 4; ++j) acc[i][j] = 0.f;

    #pragma unroll
    for (int k = 0; k < 64; ++k) {
        float4 xv = *(const float4*)&rs[k][ty * 4];
        float4 wv = *(const float4*)&ws[k][tx * 4];
        float ax[4] = {xv.x, xv.y, xv.z, xv.w};
        float aw[4] = {wv.x, wv.y, wv.z, wv.w};
        #pragma unroll
        for (int i = 0; i < 4; ++i)
            #pragma unroll
            for (int j = 0; j < 4; ++j) acc[i][j] += ax[i] * aw[j];
    }

    float4 bb = __ldg((const float4*)b + tx);
    #pragma unroll
    for (int i = 0; i < 4; ++i) {
        int row = row0 + ty * 4 + i;
        if (row < n) {
            __half2 p0 = __floats2half2_rn(acc[i][0] + bb.x, acc[i][1] + bb.y);
            __half2 p1 = __floats2half2_rn(acc[i][2] + bb.z, acc[i][3] + bb.w);
            uint2 o;
            o.x = *(unsigned*)&p0; o.y = *(unsigned*)&p1;
            g_h2h[row * 10 + tx] = o;
        }
    }
}

// ------- agg2+logsoftmax: out = log_softmax((h2[row]+sum h2[csr])/cnt)
// warp/row, 10 lanes/edge x 3 groups, fused epilogue
__global__ __launch_bounds__(256) void k_agg2(float* __restrict__ out, int n) {
    int row = (blockIdx.x * 256 + threadIdx.x) >> 5;
    if (row >= n) return;
    int lane = threadIdx.x & 31;
    int grp = lane / 10, sub = lane - grp * 10;   // grp 3 (lanes 30,31) idle
    int start = g_off[row], deg = g_deg[row], end = start + deg;

    float acc[4] = {0.f, 0.f, 0.f, 0.f};
    if (lane < 30) {
        for (int j = start + grp; j < end; j += 3) {
            int s = __ldg(&g_csr[j]);
            uint2 v = __ldg(&g_h2h[s * 10 + sub]);
            float2 f0 = __half22float2(*(__half2*)&v.x);
            float2 f1 = __half22float2(*(__half2*)&v.y);
            acc[0] += f0.x; acc[1] += f0.y; acc[2] += f1.x; acc[3] += f1.y;
        }
    }
    #pragma unroll
    for (int i = 0; i < 4; ++i) {
        float a1 = __shfl_sync(0xFFFFFFFFu, acc[i], lane + 10);
        float a2 = __shfl_sync(0xFFFFFFFFu, acc[i], lane + 20);
        acc[i] = acc[i] + a1 + a2;     // valid for lanes 0-9
    }

    bool act = (lane < 10);
    float x[4];
    float inv = 1.0f / (float)(deg + 1);
    if (act) {
        uint2 h = g_h2h[row * 10 + lane];
        float2 f0 = __half22float2(*(__half2*)&h.x);
        float2 f1 = __half22float2(*(__half2*)&h.y);
        x[0] = (acc[0] + f0.x) * inv;
        x[1] = (acc[1] + f0.y) * inv;
        x[2] = (acc[2] + f1.x) * inv;
        x[3] = (acc[3] + f1.y) * inv;
    } else {
        x[0] = x[1] = x[2] = x[3] = -3.4e38f;
    }
    float m = fmaxf(fmaxf(x[0], x[1]), fmaxf(x[2], x[3]));
    #pragma unroll
    for (int o = 16; o > 0; o >>= 1)
        m = fmaxf(m, __shfl_xor_sync(0xFFFFFFFFu, m, o));
    float s = act ? (expf(x[0] - m) + expf(x[1] - m) +
                     expf(x[2] - m) + expf(x[3] - m)) : 0.f;
    #pragma unroll
    for (int o = 16; o > 0; o >>= 1)
        s += __shfl_xor_sync(0xFFFFFFFFu, s, o);
    float l = m + logf(s);
    if (act) {
        float4 o4;
        o4.x = x[0] - l; o4.y = x[1] - l; o4.z = x[2] - l; o4.w = x[3] - l;
        ((float4*)(out + (size_t)row * NCLS))[lane] = o4;
    }
}

// ---------------- launch ----------------
extern "C" void kernel_launch(void* const* d_in, const int* in_sizes, int n_in,
                              void* d_out, int out_size)
{
    const float* x  = (const float*)d_in[0];
    const void*  ei = d_in[1];
    const float* W1 = (const float*)d_in[2];
    const float* b1 = (const float*)d_in[3];
    const float* W2 = (const float*)d_in[4];
    const float* b2 = (const float*)d_in[5];
    float* out = (float*)d_out;

    int n = in_sizes[0] / NFEAT;      // 100000
    int E = in_sizes[1] / 2;          // 1600000
    int nb = (n + 255) / 256;         // 391

    k_pre  <<<nb, 256>>>((const unsigned*)ei, n);
    k_hist <<<(E + 255) / 256, 256>>>(ei, E);
    k_scan1<<<nb, 256>>>(n);
    k_scan2<<<1, 512>>>(nb);
    k_scan3<<<nb, 256>>>(n);
    k_csr  <<<(E + 255) / 256, 256>>>(E);

    k_gemm1<<<(n + 63) / 64, 256>>>(x, W1, b1, n);
    k_agg1 <<<(n * 32 + 255) / 256, 256>>>(n);

    k_gemm2<<<(n + 63) / 64, 160>>>(W2, b2, n);
    k_agg2 <<<(n * 32 + 255) / 256, 256>>>(out, n);
}